// round 1
// baseline (speedup 1.0000x reference)
#include <cuda_runtime.h>
#include <cuda_bf16.h>
#include <math.h>

// Problem constants
#define BATCH 32
#define DMODEL 384
#define NHEAD 8
#define HDIM 48
#define NS_TOK 1024   // 32x32 search
#define NT_TOK 256    // 16x16 target
#define NTOK 1280     // NS+NT
#define KV_S 256      // 16x16 search kv
#define KV_T 64       // 8x8 target kv
#define KVTOK 320
#define FFDIM 1536
#define ATT_SCALE 0.14433756729740643f  // 1/sqrt(48)
#define EPS_LN 1e-5f
#define EPS_BN 1e-5f

// -------- scratch (device globals; no allocation allowed) --------
__device__ float g_xn[(size_t)BATCH * NTOK * DMODEL];
__device__ float g_cq[(size_t)BATCH * NTOK * DMODEL];
__device__ float g_ck[(size_t)BATCH * KVTOK * DMODEL];
__device__ float g_cv[(size_t)BATCH * KVTOK * DMODEL];
__device__ float g_q [(size_t)BATCH * NTOK * DMODEL];
__device__ float g_k [(size_t)BATCH * KVTOK * DMODEL];
__device__ float g_v [(size_t)BATCH * KVTOK * DMODEL];
__device__ float g_x1[(size_t)BATCH * NTOK * DMODEL];
__device__ float g_l2[(size_t)BATCH * NTOK * DMODEL];
__device__ float g_h [(size_t)BATCH * NTOK * FFDIM];

// ======================= LayerNorm (one block / token) =======================
__global__ void ln_kernel(const float* __restrict__ X, const float* __restrict__ gg,
                          const float* __restrict__ bb, float* __restrict__ Y) {
    int row = blockIdx.x, t = threadIdx.x;   // 128 threads
    const float* xp = X + (size_t)row * DMODEL;
    float v[3];
    float s = 0.f, ss = 0.f;
#pragma unroll
    for (int i = 0; i < 3; i++) { v[i] = xp[t + i * 128]; s += v[i]; ss += v[i] * v[i]; }
#pragma unroll
    for (int off = 16; off > 0; off >>= 1) {
        s  += __shfl_xor_sync(0xffffffffu, s,  off);
        ss += __shfl_xor_sync(0xffffffffu, ss, off);
    }
    __shared__ float sm[4], sm2[4];
    int wid = t >> 5;
    if ((t & 31) == 0) { sm[wid] = s; sm2[wid] = ss; }
    __syncthreads();
    s  = sm[0] + sm[1] + sm[2] + sm[3];
    ss = sm2[0] + sm2[1] + sm2[2] + sm2[3];
    float mean = s * (1.0f / DMODEL);
    float var  = ss * (1.0f / DMODEL) - mean * mean;
    float r = rsqrtf(var + EPS_LN);
    float* yp = Y + (size_t)row * DMODEL;
#pragma unroll
    for (int i = 0; i < 3; i++) {
        int c = t + i * 128;
        yp[c] = (v[i] - mean) * r * gg[c] + bb[c];
    }
}

// ================= Depthwise 3x3 conv + BN, stride 1 (Q path) ================
// grid: (NTOK, BATCH), block: 384 (one thread per channel)
__global__ void convq_kernel(const float* __restrict__ xn, const float* __restrict__ w,
                             const float* __restrict__ cb, const float* __restrict__ g,
                             const float* __restrict__ bb, float* __restrict__ out) {
    int b = blockIdx.y, tok = blockIdx.x, c = threadIdx.x;
    int Wd, base;
    if (tok < NS_TOK) { Wd = 32; base = 0; } else { Wd = 16; base = NS_TOK; }
    int loc = tok - base;
    int oy = loc / Wd, ox = loc % Wd;
    const float* wp = w + c * 9;
    float acc = 0.f;
#pragma unroll
    for (int ky = 0; ky < 3; ky++) {
        int iy = oy - 1 + ky;
        if (iy < 0 || iy >= Wd) continue;
#pragma unroll
        for (int kx = 0; kx < 3; kx++) {
            int ix = ox - 1 + kx;
            if (ix < 0 || ix >= Wd) continue;
            acc += wp[ky * 3 + kx] * xn[((size_t)b * NTOK + base + iy * Wd + ix) * DMODEL + c];
        }
    }
    float sc = g[c] * rsqrtf(1.0f + EPS_BN);
    out[((size_t)b * NTOK + tok) * DMODEL + c] = (acc + cb[c]) * sc + bb[c];
}

// ============ Depthwise 3x3 conv + BN, stride 2, fused K & V =================
// grid: (KVTOK, BATCH), block: 384
__global__ void convkv_kernel(const float* __restrict__ xn,
                              const float* __restrict__ wk, const float* __restrict__ cbk,
                              const float* __restrict__ gk, const float* __restrict__ bbk,
                              const float* __restrict__ wv, const float* __restrict__ cbv,
                              const float* __restrict__ gv, const float* __restrict__ bbv,
                              float* __restrict__ outk, float* __restrict__ outv) {
    int b = blockIdx.y, tok = blockIdx.x, c = threadIdx.x;
    int Wd, inW, inBase, base;
    if (tok < KV_S) { Wd = 16; inW = 32; inBase = 0; base = 0; }
    else            { Wd = 8;  inW = 16; inBase = NS_TOK; base = KV_S; }
    int loc = tok - base;
    int oy = loc / Wd, ox = loc % Wd;
    const float* wpk = wk + c * 9;
    const float* wpv = wv + c * 9;
    float acck = 0.f, accv = 0.f;
#pragma unroll
    for (int ky = 0; ky < 3; ky++) {
        int iy = 2 * oy - 1 + ky;
        if (iy < 0 || iy >= inW) continue;
#pragma unroll
        for (int kx = 0; kx < 3; kx++) {
            int ix = 2 * ox - 1 + kx;
            if (ix < 0 || ix >= inW) continue;
            float xv = xn[((size_t)b * NTOK + inBase + iy * inW + ix) * DMODEL + c];
            acck += wpk[ky * 3 + kx] * xv;
            accv += wpv[ky * 3 + kx] * xv;
        }
    }
    size_t oidx = ((size_t)b * KVTOK + tok) * DMODEL + c;
    outk[oidx] = (acck + cbk[c]) * (gk[c] * rsqrtf(1.0f + EPS_BN)) + bbk[c];
    outv[oidx] = (accv + cbv[c]) * (gv[c] * rsqrtf(1.0f + EPS_BN)) + bbv[c];
}

// ======================= Tiled GEMM: C = A @ W^T + bias ======================
// A[M,K] row-major, W[N,K] row-major. 128x128x16 tiles, 256 threads, 8x8 micro.
// EPI: 0 none, 1 gelu(exact), 2 residual add (resid[M,N]).
#define BM 128
#define BN 128
#define BK 16
#define TSTR 132  // 128+4 pad

template<int EPI>
__global__ void gemm_kernel(const float* __restrict__ A, const float* __restrict__ W,
                            const float* __restrict__ bias, const float* __restrict__ resid,
                            float* __restrict__ C, int M, int Nn, int Kk) {
    __shared__ float As[BK][TSTR];
    __shared__ float Ws[BK][TSTR];
    int t = threadIdx.x;
    int tx = t & 15, ty = t >> 4;
    int bm = blockIdx.y * BM, bn = blockIdx.x * BN;
    const float* Ap = A + (size_t)bm * Kk;
    const float* Wp = W + (size_t)bn * Kk;
    float acc[8][8];
#pragma unroll
    for (int i = 0; i < 8; i++)
#pragma unroll
        for (int j = 0; j < 8; j++) acc[i][j] = 0.f;

    for (int k0 = 0; k0 < Kk; k0 += BK) {
#pragma unroll
        for (int i = 0; i < 8; i++) {
            int e = t + i * 256;
            int r = e >> 4, c = e & 15;
            As[c][r] = Ap[(size_t)r * Kk + k0 + c];
            Ws[c][r] = Wp[(size_t)r * Kk + k0 + c];
        }
        __syncthreads();
#pragma unroll
        for (int k = 0; k < BK; k++) {
            float4 a0 = *(const float4*)&As[k][ty * 8];
            float4 a1 = *(const float4*)&As[k][ty * 8 + 4];
            float4 w0 = *(const float4*)&Ws[k][tx * 8];
            float4 w1 = *(const float4*)&Ws[k][tx * 8 + 4];
            float av[8] = {a0.x, a0.y, a0.z, a0.w, a1.x, a1.y, a1.z, a1.w};
            float wv[8] = {w0.x, w0.y, w0.z, w0.w, w1.x, w1.y, w1.z, w1.w};
#pragma unroll
            for (int i = 0; i < 8; i++)
#pragma unroll
                for (int j = 0; j < 8; j++) acc[i][j] += av[i] * wv[j];
        }
        __syncthreads();
    }
#pragma unroll
    for (int i = 0; i < 8; i++) {
        int m = bm + ty * 8 + i;
#pragma unroll
        for (int j = 0; j < 8; j++) {
            int n = bn + tx * 8 + j;
            float vv = acc[i][j] + bias[n];
            if (EPI == 1) {
                vv = 0.5f * vv * (1.0f + erff(vv * 0.70710678118654752f));
            } else if (EPI == 2) {
                vv += resid[(size_t)m * Nn + n];
            }
            C[(size_t)m * Nn + n] = vv;
        }
    }
}

// =========================== Flash-style attention ===========================
// grid: (nq/16, NHEAD, BATCH), block 128. 8 threads per query.
// Q rows: [B*NTOK, D]; K/V rows: [B*KVTOK, D]; head h slice = cols h*48..h*48+47.
#define QB 16
#define KSTR 52   // 48 padded to mult-of-4, conflict-free for float4 row reads

__global__ void attn_kernel(const float* __restrict__ Q, const float* __restrict__ Kt,
                            const float* __restrict__ V, const float* __restrict__ X,
                            float* __restrict__ O,
                            int q_off, int kv_off, int kv_len) {
    int b = blockIdx.z, h = blockIdx.y;
    int qbase = q_off + blockIdx.x * QB;
    int t = threadIdx.x;
    __shared__ float qs[QB][KSTR];
    __shared__ float ks[32][KSTR];
    __shared__ float vs[32][KSTR];
    __shared__ float Ps[QB][33];
    __shared__ float mrow[QB], lrow[QB];

    // load Q tile
    for (int e = t; e < QB * HDIM; e += 128) {
        int r = e / HDIM, c = e % HDIM;
        qs[r][c] = Q[((size_t)(b * NTOK + qbase + r)) * DMODEL + h * HDIM + c];
    }
    if (t < QB) { mrow[t] = -1e30f; lrow[t] = 0.f; }
    int qi = t >> 3;
    int lane8 = t & 7;
    int dbase = lane8 * 6;
    float o[6] = {0.f, 0.f, 0.f, 0.f, 0.f, 0.f};
    __syncthreads();

    for (int kt = 0; kt < kv_len; kt += 32) {
        for (int e = t; e < 32 * HDIM; e += 128) {
            int r = e / HDIM, c = e % HDIM;
            size_t gidx = ((size_t)(b * KVTOK + kv_off + kt + r)) * DMODEL + h * HDIM + c;
            ks[r][c] = Kt[gidx];
            vs[r][c] = V[gidx];
        }
        __syncthreads();

        // scores: 4 kv per thread (kj = lane8 + 8r)
        float s0 = 0.f, s1 = 0.f, s2 = 0.f, s3 = 0.f;
#pragma unroll
        for (int d = 0; d < HDIM; d += 4) {
            float4 qv = *(const float4*)&qs[qi][d];
            float4 k0 = *(const float4*)&ks[lane8][d];
            float4 k1 = *(const float4*)&ks[lane8 + 8][d];
            float4 k2 = *(const float4*)&ks[lane8 + 16][d];
            float4 k3 = *(const float4*)&ks[lane8 + 24][d];
            s0 += qv.x * k0.x + qv.y * k0.y + qv.z * k0.z + qv.w * k0.w;
            s1 += qv.x * k1.x + qv.y * k1.y + qv.z * k1.z + qv.w * k1.w;
            s2 += qv.x * k2.x + qv.y * k2.y + qv.z * k2.z + qv.w * k2.w;
            s3 += qv.x * k3.x + qv.y * k3.y + qv.z * k3.z + qv.w * k3.w;
        }
        s0 *= ATT_SCALE; s1 *= ATT_SCALE; s2 *= ATT_SCALE; s3 *= ATT_SCALE;

        float mt = fmaxf(fmaxf(s0, s1), fmaxf(s2, s3));
#pragma unroll
        for (int off = 1; off < 8; off <<= 1)
            mt = fmaxf(mt, __shfl_xor_sync(0xffffffffu, mt, off));
        float mold = mrow[qi];
        float mnew = fmaxf(mold, mt);
        float p0 = __expf(s0 - mnew), p1 = __expf(s1 - mnew);
        float p2 = __expf(s2 - mnew), p3 = __expf(s3 - mnew);
        float psum = p0 + p1 + p2 + p3;
#pragma unroll
        for (int off = 1; off < 8; off <<= 1)
            psum += __shfl_xor_sync(0xffffffffu, psum, off);
        float corr = __expf(mold - mnew);
        Ps[qi][lane8] = p0; Ps[qi][lane8 + 8] = p1;
        Ps[qi][lane8 + 16] = p2; Ps[qi][lane8 + 24] = p3;
#pragma unroll
        for (int j = 0; j < 6; j++) o[j] *= corr;
        __syncwarp();
        if (lane8 == 0) { lrow[qi] = lrow[qi] * corr + psum; mrow[qi] = mnew; }

        // o += P @ V  (thread owns dims dbase..dbase+5 of query qi)
#pragma unroll
        for (int kj = 0; kj < 32; kj++) {
            float pv = Ps[qi][kj];
            float2 v0 = *(const float2*)&vs[kj][dbase];
            float2 v1 = *(const float2*)&vs[kj][dbase + 2];
            float2 v2 = *(const float2*)&vs[kj][dbase + 4];
            o[0] += pv * v0.x; o[1] += pv * v0.y;
            o[2] += pv * v1.x; o[3] += pv * v1.y;
            o[4] += pv * v2.x; o[5] += pv * v2.y;
        }
        __syncthreads();
    }

    float linv = 1.0f / lrow[qi];
    size_t base = ((size_t)(b * NTOK + qbase + qi)) * DMODEL + h * HDIM + dbase;
#pragma unroll
    for (int j = 0; j < 6; j++)
        O[base + j] = X[base + j] + o[j] * linv;
}

// ================================ launch =====================================
extern "C" void kernel_launch(void* const* d_in, const int* in_sizes, int n_in,
                              void* d_out, int out_size) {
    const float* x     = (const float*)d_in[0];
    const float* ln1_g = (const float*)d_in[1];
    const float* ln1_b = (const float*)d_in[2];
    const float* dwq_w = (const float*)d_in[3];
    const float* dwq_b = (const float*)d_in[4];
    const float* bnq_g = (const float*)d_in[5];
    const float* bnq_b = (const float*)d_in[6];
    const float* dwk_w = (const float*)d_in[7];
    const float* dwk_b = (const float*)d_in[8];
    const float* bnk_g = (const float*)d_in[9];
    const float* bnk_b = (const float*)d_in[10];
    const float* dwv_w = (const float*)d_in[11];
    const float* dwv_b = (const float*)d_in[12];
    const float* bnv_g = (const float*)d_in[13];
    const float* bnv_b = (const float*)d_in[14];
    const float* pq_w  = (const float*)d_in[15];
    const float* pq_b  = (const float*)d_in[16];
    const float* pk_w  = (const float*)d_in[17];
    const float* pk_b  = (const float*)d_in[18];
    const float* pv_w  = (const float*)d_in[19];
    const float* pv_b  = (const float*)d_in[20];
    const float* ln2_g = (const float*)d_in[21];
    const float* ln2_b = (const float*)d_in[22];
    const float* ff1_w = (const float*)d_in[23];
    const float* ff1_b = (const float*)d_in[24];
    const float* ff2_w = (const float*)d_in[25];
    const float* ff2_b = (const float*)d_in[26];
    float* out = (float*)d_out;

    float *xn, *cq, *ck, *cv, *q, *k, *v, *x1, *l2, *hbuf;
    cudaGetSymbolAddress((void**)&xn,   g_xn);
    cudaGetSymbolAddress((void**)&cq,   g_cq);
    cudaGetSymbolAddress((void**)&ck,   g_ck);
    cudaGetSymbolAddress((void**)&cv,   g_cv);
    cudaGetSymbolAddress((void**)&q,    g_q);
    cudaGetSymbolAddress((void**)&k,    g_k);
    cudaGetSymbolAddress((void**)&v,    g_v);
    cudaGetSymbolAddress((void**)&x1,   g_x1);
    cudaGetSymbolAddress((void**)&l2,   g_l2);
    cudaGetSymbolAddress((void**)&hbuf, g_h);

    const int Mq = BATCH * NTOK;    // 40960
    const int Mkv = BATCH * KVTOK;  // 10240

    // 1. LN1
    ln_kernel<<<Mq, 128>>>(x, ln1_g, ln1_b, xn);
    // 2. depthwise convs + BN
    convq_kernel<<<dim3(NTOK, BATCH), DMODEL>>>(xn, dwq_w, dwq_b, bnq_g, bnq_b, cq);
    convkv_kernel<<<dim3(KVTOK, BATCH), DMODEL>>>(xn, dwk_w, dwk_b, bnk_g, bnk_b,
                                                  dwv_w, dwv_b, bnv_g, bnv_b, ck, cv);
    // 3. projections
    gemm_kernel<0><<<dim3(DMODEL / BN, Mq / BM), 256>>>(cq, pq_w, pq_b, nullptr, q, Mq, DMODEL, DMODEL);
    gemm_kernel<0><<<dim3(DMODEL / BN, Mkv / BM), 256>>>(ck, pk_w, pk_b, nullptr, k, Mkv, DMODEL, DMODEL);
    gemm_kernel<0><<<dim3(DMODEL / BN, Mkv / BM), 256>>>(cv, pv_w, pv_b, nullptr, v, Mkv, DMODEL, DMODEL);
    // 4. attention + residual -> x1
    attn_kernel<<<dim3(NS_TOK / QB, NHEAD, BATCH), 128>>>(q, k, v, x, x1, 0, 0, KVTOK);
    attn_kernel<<<dim3(NT_TOK / QB, NHEAD, BATCH), 128>>>(q, k, v, x, x1, NS_TOK, KV_S, KV_T);
    // 5. LN2
    ln_kernel<<<Mq, 128>>>(x1, ln2_g, ln2_b, l2);
    // 6. FFN
    gemm_kernel<1><<<dim3(FFDIM / BN, Mq / BM), 256>>>(l2, ff1_w, ff1_b, nullptr, hbuf, Mq, FFDIM, DMODEL);
    gemm_kernel<2><<<dim3(DMODEL / BN, Mq / BM), 256>>>(hbuf, ff2_w, ff2_b, x1, out, Mq, DMODEL, FFDIM);
}

// round 2
// speedup vs baseline: 1.8513x; 1.8513x over previous
#include <cuda_runtime.h>
#include <cuda_bf16.h>
#include <math.h>
#include <stdint.h>

// Problem constants
#define BATCH 32
#define DMODEL 384
#define NHEAD 8
#define HDIM 48
#define NS_TOK 1024   // 32x32 search
#define NT_TOK 256    // 16x16 target
#define NTOK 1280     // NS+NT
#define KV_S 256      // 16x16 search kv
#define KV_T 64       // 8x8 target kv
#define KVTOK 320
#define FFDIM 1536
#define ATT_SCALE 0.14433756729740643f  // 1/sqrt(48)
#define EPS_LN 1e-5f
#define EPS_BN 1e-5f

// -------- scratch (device globals; no allocation allowed) --------
__device__ float g_xn[(size_t)BATCH * NTOK * DMODEL];
__device__ float g_cq[(size_t)BATCH * NTOK * DMODEL];
__device__ float g_ck[(size_t)BATCH * KVTOK * DMODEL];
__device__ float g_cv[(size_t)BATCH * KVTOK * DMODEL];
__device__ float g_q [(size_t)BATCH * NTOK * DMODEL];
__device__ float g_k [(size_t)BATCH * KVTOK * DMODEL];
__device__ float g_v [(size_t)BATCH * KVTOK * DMODEL];
__device__ float g_x1[(size_t)BATCH * NTOK * DMODEL];
__device__ float g_l2[(size_t)BATCH * NTOK * DMODEL];
__device__ float g_h [(size_t)BATCH * NTOK * FFDIM];

// ======================= LayerNorm (one block / token) =======================
__global__ void ln_kernel(const float* __restrict__ X, const float* __restrict__ gg,
                          const float* __restrict__ bb, float* __restrict__ Y) {
    int row = blockIdx.x, t = threadIdx.x;   // 128 threads
    const float* xp = X + (size_t)row * DMODEL;
    float v[3];
    float s = 0.f, ss = 0.f;
#pragma unroll
    for (int i = 0; i < 3; i++) { v[i] = xp[t + i * 128]; s += v[i]; ss += v[i] * v[i]; }
#pragma unroll
    for (int off = 16; off > 0; off >>= 1) {
        s  += __shfl_xor_sync(0xffffffffu, s,  off);
        ss += __shfl_xor_sync(0xffffffffu, ss, off);
    }
    __shared__ float sm[4], sm2[4];
    int wid = t >> 5;
    if ((t & 31) == 0) { sm[wid] = s; sm2[wid] = ss; }
    __syncthreads();
    s  = sm[0] + sm[1] + sm[2] + sm[3];
    ss = sm2[0] + sm2[1] + sm2[2] + sm2[3];
    float mean = s * (1.0f / DMODEL);
    float var  = ss * (1.0f / DMODEL) - mean * mean;
    float r = rsqrtf(var + EPS_LN);
    float* yp = Y + (size_t)row * DMODEL;
#pragma unroll
    for (int i = 0; i < 3; i++) {
        int c = t + i * 128;
        yp[c] = (v[i] - mean) * r * gg[c] + bb[c];
    }
}

// ================= Depthwise 3x3 conv + BN, stride 1 (Q path) ================
__global__ void convq_kernel(const float* __restrict__ xn, const float* __restrict__ w,
                             const float* __restrict__ cb, const float* __restrict__ g,
                             const float* __restrict__ bb, float* __restrict__ out) {
    int b = blockIdx.y, tok = blockIdx.x, c = threadIdx.x;
    int Wd, base;
    if (tok < NS_TOK) { Wd = 32; base = 0; } else { Wd = 16; base = NS_TOK; }
    int loc = tok - base;
    int oy = loc / Wd, ox = loc % Wd;
    const float* wp = w + c * 9;
    float acc = 0.f;
#pragma unroll
    for (int ky = 0; ky < 3; ky++) {
        int iy = oy - 1 + ky;
        if (iy < 0 || iy >= Wd) continue;
#pragma unroll
        for (int kx = 0; kx < 3; kx++) {
            int ix = ox - 1 + kx;
            if (ix < 0 || ix >= Wd) continue;
            acc += wp[ky * 3 + kx] * xn[((size_t)b * NTOK + base + iy * Wd + ix) * DMODEL + c];
        }
    }
    float sc = g[c] * rsqrtf(1.0f + EPS_BN);
    out[((size_t)b * NTOK + tok) * DMODEL + c] = (acc + cb[c]) * sc + bb[c];
}

// ============ Depthwise 3x3 conv + BN, stride 2, fused K & V =================
__global__ void convkv_kernel(const float* __restrict__ xn,
                              const float* __restrict__ wk, const float* __restrict__ cbk,
                              const float* __restrict__ gk, const float* __restrict__ bbk,
                              const float* __restrict__ wv, const float* __restrict__ cbv,
                              const float* __restrict__ gv, const float* __restrict__ bbv,
                              float* __restrict__ outk, float* __restrict__ outv) {
    int b = blockIdx.y, tok = blockIdx.x, c = threadIdx.x;
    int Wd, inW, inBase, base;
    if (tok < KV_S) { Wd = 16; inW = 32; inBase = 0; base = 0; }
    else            { Wd = 8;  inW = 16; inBase = NS_TOK; base = KV_S; }
    int loc = tok - base;
    int oy = loc / Wd, ox = loc % Wd;
    const float* wpk = wk + c * 9;
    const float* wpv = wv + c * 9;
    float acck = 0.f, accv = 0.f;
#pragma unroll
    for (int ky = 0; ky < 3; ky++) {
        int iy = 2 * oy - 1 + ky;
        if (iy < 0 || iy >= inW) continue;
#pragma unroll
        for (int kx = 0; kx < 3; kx++) {
            int ix = 2 * ox - 1 + kx;
            if (ix < 0 || ix >= inW) continue;
            float xv = xn[((size_t)b * NTOK + inBase + iy * inW + ix) * DMODEL + c];
            acck += wpk[ky * 3 + kx] * xv;
            accv += wpv[ky * 3 + kx] * xv;
        }
    }
    size_t oidx = ((size_t)b * KVTOK + tok) * DMODEL + c;
    outk[oidx] = (acck + cbk[c]) * (gk[c] * rsqrtf(1.0f + EPS_BN)) + bbk[c];
    outv[oidx] = (accv + cbv[c]) * (gv[c] * rsqrtf(1.0f + EPS_BN)) + bbv[c];
}

// ================== TF32 tensor-core GEMM: C = A @ W^T + bias ================
// A[M,K] row-major, W[N,K] row-major. 128x128x32 tiles, 256 threads (8 warps),
// warp tile 64x32 via mma.sync.m16n8k8 tf32. EPI: 0 none, 1 gelu, 2 +resid.
#define BM 128
#define BN 128
#define BK 32
#define SSTR 36   // BK+4: bank = (4*row + col) % 32 -> conflict-free frag loads

__device__ __forceinline__ uint32_t f2tf32(float x) {
    uint32_t u;
    asm("cvt.rna.tf32.f32 %0, %1;" : "=r"(u) : "f"(x));
    return u;
}

template<int EPI>
__global__ void __launch_bounds__(256) gemm_tc(
        const float* __restrict__ A, const float* __restrict__ W,
        const float* __restrict__ bias, const float* __restrict__ resid,
        float* __restrict__ C, int M, int Nn, int Kk) {
    __shared__ uint32_t As[BM][SSTR];
    __shared__ uint32_t Ws[BN][SSTR];
    int t = threadIdx.x;
    int lane = t & 31, wid = t >> 5;
    int wm = (wid & 1) * 64;     // warp row offset in tile
    int wn = (wid >> 1) * 32;    // warp col offset in tile
    int bm = blockIdx.y * BM, bn = blockIdx.x * BN;

    float acc[4][4][4];          // [mi][ni][frag]
#pragma unroll
    for (int mi = 0; mi < 4; mi++)
#pragma unroll
        for (int ni = 0; ni < 4; ni++)
#pragma unroll
            for (int f = 0; f < 4; f++) acc[mi][ni][f] = 0.f;

    int lr = lane >> 2;          // 0..7
    int lc = lane & 3;           // 0..3

    for (int k0 = 0; k0 < Kk; k0 += BK) {
        // ---- global -> smem (with tf32 convert), 4 float4 per thread each ----
#pragma unroll
        for (int i = 0; i < 4; i++) {
            int e = t + i * 256;          // float4 index, 8 per row
            int r = e >> 3, c4 = (e & 7) * 4;
            float4 av = *(const float4*)&A[(size_t)(bm + r) * Kk + k0 + c4];
            uint4 au = {f2tf32(av.x), f2tf32(av.y), f2tf32(av.z), f2tf32(av.w)};
            *(uint4*)&As[r][c4] = au;
            float4 wv = *(const float4*)&W[(size_t)(bn + r) * Kk + k0 + c4];
            uint4 wu = {f2tf32(wv.x), f2tf32(wv.y), f2tf32(wv.z), f2tf32(wv.w)};
            *(uint4*)&Ws[r][c4] = wu;
        }
        __syncthreads();

#pragma unroll
        for (int ks = 0; ks < BK; ks += 8) {
            uint32_t af[4][4], bf[4][2];
#pragma unroll
            for (int mi = 0; mi < 4; mi++) {
                int row = wm + mi * 16 + lr;
                af[mi][0] = As[row][ks + lc];
                af[mi][1] = As[row + 8][ks + lc];
                af[mi][2] = As[row][ks + lc + 4];
                af[mi][3] = As[row + 8][ks + lc + 4];
            }
#pragma unroll
            for (int ni = 0; ni < 4; ni++) {
                int n = wn + ni * 8 + lr;
                bf[ni][0] = Ws[n][ks + lc];
                bf[ni][1] = Ws[n][ks + lc + 4];
            }
#pragma unroll
            for (int mi = 0; mi < 4; mi++)
#pragma unroll
                for (int ni = 0; ni < 4; ni++) {
                    asm volatile(
                        "mma.sync.aligned.m16n8k8.row.col.f32.tf32.tf32.f32 "
                        "{%0,%1,%2,%3}, {%4,%5,%6,%7}, {%8,%9}, {%0,%1,%2,%3};\n"
                        : "+f"(acc[mi][ni][0]), "+f"(acc[mi][ni][1]),
                          "+f"(acc[mi][ni][2]), "+f"(acc[mi][ni][3])
                        : "r"(af[mi][0]), "r"(af[mi][1]), "r"(af[mi][2]), "r"(af[mi][3]),
                          "r"(bf[ni][0]), "r"(bf[ni][1]));
                }
        }
        __syncthreads();
    }

    // ---- epilogue ----
#pragma unroll
    for (int mi = 0; mi < 4; mi++) {
#pragma unroll
        for (int ni = 0; ni < 4; ni++) {
            int r0 = bm + wm + mi * 16 + lr;
            int cc = bn + wn + ni * 8 + 2 * lc;
            float b0 = bias[cc], b1 = bias[cc + 1];
#pragma unroll
            for (int half = 0; half < 2; half++) {
                int r = r0 + half * 8;
                float v0 = acc[mi][ni][half * 2 + 0] + b0;
                float v1 = acc[mi][ni][half * 2 + 1] + b1;
                if (EPI == 1) {
                    v0 = 0.5f * v0 * (1.0f + erff(v0 * 0.70710678118654752f));
                    v1 = 0.5f * v1 * (1.0f + erff(v1 * 0.70710678118654752f));
                } else if (EPI == 2) {
                    const float2 rv = *(const float2*)&resid[(size_t)r * Nn + cc];
                    v0 += rv.x; v1 += rv.y;
                }
                float2 ov = {v0, v1};
                *(float2*)&C[(size_t)r * Nn + cc] = ov;
            }
        }
    }
}

// =========================== Flash-style attention ===========================
#define QB 16
#define KSTR 52

__global__ void attn_kernel(const float* __restrict__ Q, const float* __restrict__ Kt,
                            const float* __restrict__ V, const float* __restrict__ X,
                            float* __restrict__ O,
                            int q_off, int kv_off, int kv_len) {
    int b = blockIdx.z, h = blockIdx.y;
    int qbase = q_off + blockIdx.x * QB;
    int t = threadIdx.x;
    __shared__ float qs[QB][KSTR];
    __shared__ float ks[32][KSTR];
    __shared__ float vs[32][KSTR];
    __shared__ float Ps[QB][33];
    __shared__ float mrow[QB], lrow[QB];

    for (int e = t; e < QB * HDIM; e += 128) {
        int r = e / HDIM, c = e % HDIM;
        qs[r][c] = Q[((size_t)(b * NTOK + qbase + r)) * DMODEL + h * HDIM + c];
    }
    if (t < QB) { mrow[t] = -1e30f; lrow[t] = 0.f; }
    int qi = t >> 3;
    int lane8 = t & 7;
    int dbase = lane8 * 6;
    float o[6] = {0.f, 0.f, 0.f, 0.f, 0.f, 0.f};
    __syncthreads();

    for (int kt = 0; kt < kv_len; kt += 32) {
        for (int e = t; e < 32 * HDIM; e += 128) {
            int r = e / HDIM, c = e % HDIM;
            size_t gidx = ((size_t)(b * KVTOK + kv_off + kt + r)) * DMODEL + h * HDIM + c;
            ks[r][c] = Kt[gidx];
            vs[r][c] = V[gidx];
        }
        __syncthreads();

        float s0 = 0.f, s1 = 0.f, s2 = 0.f, s3 = 0.f;
#pragma unroll
        for (int d = 0; d < HDIM; d += 4) {
            float4 qv = *(const float4*)&qs[qi][d];
            float4 k0 = *(const float4*)&ks[lane8][d];
            float4 k1 = *(const float4*)&ks[lane8 + 8][d];
            float4 k2 = *(const float4*)&ks[lane8 + 16][d];
            float4 k3 = *(const float4*)&ks[lane8 + 24][d];
            s0 += qv.x * k0.x + qv.y * k0.y + qv.z * k0.z + qv.w * k0.w;
            s1 += qv.x * k1.x + qv.y * k1.y + qv.z * k1.z + qv.w * k1.w;
            s2 += qv.x * k2.x + qv.y * k2.y + qv.z * k2.z + qv.w * k2.w;
            s3 += qv.x * k3.x + qv.y * k3.y + qv.z * k3.z + qv.w * k3.w;
        }
        s0 *= ATT_SCALE; s1 *= ATT_SCALE; s2 *= ATT_SCALE; s3 *= ATT_SCALE;

        float mt = fmaxf(fmaxf(s0, s1), fmaxf(s2, s3));
#pragma unroll
        for (int off = 1; off < 8; off <<= 1)
            mt = fmaxf(mt, __shfl_xor_sync(0xffffffffu, mt, off));
        float mold = mrow[qi];
        float mnew = fmaxf(mold, mt);
        float p0 = __expf(s0 - mnew), p1 = __expf(s1 - mnew);
        float p2 = __expf(s2 - mnew), p3 = __expf(s3 - mnew);
        float psum = p0 + p1 + p2 + p3;
#pragma unroll
        for (int off = 1; off < 8; off <<= 1)
            psum += __shfl_xor_sync(0xffffffffu, psum, off);
        float corr = __expf(mold - mnew);
        Ps[qi][lane8] = p0; Ps[qi][lane8 + 8] = p1;
        Ps[qi][lane8 + 16] = p2; Ps[qi][lane8 + 24] = p3;
#pragma unroll
        for (int j = 0; j < 6; j++) o[j] *= corr;
        __syncwarp();
        if (lane8 == 0) { lrow[qi] = lrow[qi] * corr + psum; mrow[qi] = mnew; }

#pragma unroll
        for (int kj = 0; kj < 32; kj++) {
            float pv = Ps[qi][kj];
            float2 v0 = *(const float2*)&vs[kj][dbase];
            float2 v1 = *(const float2*)&vs[kj][dbase + 2];
            float2 v2 = *(const float2*)&vs[kj][dbase + 4];
            o[0] += pv * v0.x; o[1] += pv * v0.y;
            o[2] += pv * v1.x; o[3] += pv * v1.y;
            o[4] += pv * v2.x; o[5] += pv * v2.y;
        }
        __syncthreads();
    }

    float linv = 1.0f / lrow[qi];
    size_t base = ((size_t)(b * NTOK + qbase + qi)) * DMODEL + h * HDIM + dbase;
#pragma unroll
    for (int j = 0; j < 6; j++)
        O[base + j] = X[base + j] + o[j] * linv;
}

// ================================ launch =====================================
extern "C" void kernel_launch(void* const* d_in, const int* in_sizes, int n_in,
                              void* d_out, int out_size) {
    const float* x     = (const float*)d_in[0];
    const float* ln1_g = (const float*)d_in[1];
    const float* ln1_b = (const float*)d_in[2];
    const float* dwq_w = (const float*)d_in[3];
    const float* dwq_b = (const float*)d_in[4];
    const float* bnq_g = (const float*)d_in[5];
    const float* bnq_b = (const float*)d_in[6];
    const float* dwk_w = (const float*)d_in[7];
    const float* dwk_b = (const float*)d_in[8];
    const float* bnk_g = (const float*)d_in[9];
    const float* bnk_b = (const float*)d_in[10];
    const float* dwv_w = (const float*)d_in[11];
    const float* dwv_b = (const float*)d_in[12];
    const float* bnv_g = (const float*)d_in[13];
    const float* bnv_b = (const float*)d_in[14];
    const float* pq_w  = (const float*)d_in[15];
    const float* pq_b  = (const float*)d_in[16];
    const float* pk_w  = (const float*)d_in[17];
    const float* pk_b  = (const float*)d_in[18];
    const float* pv_w  = (const float*)d_in[19];
    const float* pv_b  = (const float*)d_in[20];
    const float* ln2_g = (const float*)d_in[21];
    const float* ln2_b = (const float*)d_in[22];
    const float* ff1_w = (const float*)d_in[23];
    const float* ff1_b = (const float*)d_in[24];
    const float* ff2_w = (const float*)d_in[25];
    const float* ff2_b = (const float*)d_in[26];
    float* out = (float*)d_out;

    float *xn, *cq, *ck, *cv, *q, *k, *v, *x1, *l2, *hbuf;
    cudaGetSymbolAddress((void**)&xn,   g_xn);
    cudaGetSymbolAddress((void**)&cq,   g_cq);
    cudaGetSymbolAddress((void**)&ck,   g_ck);
    cudaGetSymbolAddress((void**)&cv,   g_cv);
    cudaGetSymbolAddress((void**)&q,    g_q);
    cudaGetSymbolAddress((void**)&k,    g_k);
    cudaGetSymbolAddress((void**)&v,    g_v);
    cudaGetSymbolAddress((void**)&x1,   g_x1);
    cudaGetSymbolAddress((void**)&l2,   g_l2);
    cudaGetSymbolAddress((void**)&hbuf, g_h);

    const int Mq = BATCH * NTOK;    // 40960
    const int Mkv = BATCH * KVTOK;  // 10240

    ln_kernel<<<Mq, 128>>>(x, ln1_g, ln1_b, xn);
    convq_kernel<<<dim3(NTOK, BATCH), DMODEL>>>(xn, dwq_w, dwq_b, bnq_g, bnq_b, cq);
    convkv_kernel<<<dim3(KVTOK, BATCH), DMODEL>>>(xn, dwk_w, dwk_b, bnk_g, bnk_b,
                                                  dwv_w, dwv_b, bnv_g, bnv_b, ck, cv);
    gemm_tc<0><<<dim3(DMODEL / BN, Mq / BM), 256>>>(cq, pq_w, pq_b, nullptr, q, Mq, DMODEL, DMODEL);
    gemm_tc<0><<<dim3(DMODEL / BN, Mkv / BM), 256>>>(ck, pk_w, pk_b, nullptr, k, Mkv, DMODEL, DMODEL);
    gemm_tc<0><<<dim3(DMODEL / BN, Mkv / BM), 256>>>(cv, pv_w, pv_b, nullptr, v, Mkv, DMODEL, DMODEL);
    attn_kernel<<<dim3(NS_TOK / QB, NHEAD, BATCH), 128>>>(q, k, v, x, x1, 0, 0, KVTOK);
    attn_kernel<<<dim3(NT_TOK / QB, NHEAD, BATCH), 128>>>(q, k, v, x, x1, NS_TOK, KV_S, KV_T);
    ln_kernel<<<Mq, 128>>>(x1, ln2_g, ln2_b, l2);
    gemm_tc<1><<<dim3(FFDIM / BN, Mq / BM), 256>>>(l2, ff1_w, ff1_b, nullptr, hbuf, Mq, FFDIM, DMODEL);
    gemm_tc<2><<<dim3(DMODEL / BN, Mq / BM), 256>>>(hbuf, ff2_w, ff2_b, x1, out, Mq, DMODEL, FFDIM);
}

// round 4
// speedup vs baseline: 3.3912x; 1.8318x over previous
#include <cuda_runtime.h>
#include <cuda_bf16.h>
#include <math.h>
#include <stdint.h>

// Problem constants
#define BATCH 32
#define DMODEL 384
#define NHEAD 8
#define HDIM 48
#define NS_TOK 1024
#define NT_TOK 256
#define NTOK 1280
#define KV_S 256
#define KV_T 64
#define KVTOK 320
#define FFDIM 1536
#define ATT_SCALE 0.14433756729740643f  // 1/sqrt(48)
#define EPS_LN 1e-5f
#define EPS_BN 1e-5f

// -------- scratch (device globals; no allocation allowed) --------
__device__ float g_xn[(size_t)BATCH * NTOK * DMODEL];
__device__ float g_cq[(size_t)BATCH * NTOK * DMODEL];
__device__ float g_ck[(size_t)BATCH * KVTOK * DMODEL];
__device__ float g_cv[(size_t)BATCH * KVTOK * DMODEL];
__device__ float g_q [(size_t)BATCH * NTOK * DMODEL];
__device__ float g_k [(size_t)BATCH * KVTOK * DMODEL];
__device__ float g_v [(size_t)BATCH * KVTOK * DMODEL];
__device__ float g_x1[(size_t)BATCH * NTOK * DMODEL];
__device__ float g_l2[(size_t)BATCH * NTOK * DMODEL];
__device__ float g_h [(size_t)BATCH * NTOK * FFDIM];

// ---------------- helpers ----------------
__device__ __forceinline__ uint32_t f2tf32(float x) {
    uint32_t u;
    asm("cvt.rna.tf32.f32 %0, %1;" : "=r"(u) : "f"(x));
    return u;
}
__device__ __forceinline__ uint32_t smem_u32(const void* p) {
    return (uint32_t)__cvta_generic_to_shared(p);
}
#define CP16(dst, src) asm volatile("cp.async.cg.shared.global [%0], [%1], 16;" :: "r"(dst), "l"(src))
#define CPCOMMIT() asm volatile("cp.async.commit_group;")

__device__ __forceinline__ void mma_tf32(float* c, const uint32_t* a, uint32_t b0, uint32_t b1) {
    asm volatile(
        "mma.sync.aligned.m16n8k8.row.col.f32.tf32.tf32.f32 "
        "{%0,%1,%2,%3}, {%4,%5,%6,%7}, {%8,%9}, {%0,%1,%2,%3};\n"
        : "+f"(c[0]), "+f"(c[1]), "+f"(c[2]), "+f"(c[3])
        : "r"(a[0]), "r"(a[1]), "r"(a[2]), "r"(a[3]), "r"(b0), "r"(b1));
}

// ======================= LayerNorm (one block / token) =======================
__global__ void ln_kernel(const float* __restrict__ X, const float* __restrict__ gg,
                          const float* __restrict__ bb, float* __restrict__ Y) {
    int row = blockIdx.x, t = threadIdx.x;   // 128 threads
    const float* xp = X + (size_t)row * DMODEL;
    float v[3];
    float s = 0.f, ss = 0.f;
#pragma unroll
    for (int i = 0; i < 3; i++) { v[i] = xp[t + i * 128]; s += v[i]; ss += v[i] * v[i]; }
#pragma unroll
    for (int off = 16; off > 0; off >>= 1) {
        s  += __shfl_xor_sync(0xffffffffu, s,  off);
        ss += __shfl_xor_sync(0xffffffffu, ss, off);
    }
    __shared__ float sm[4], sm2[4];
    int wid = t >> 5;
    if ((t & 31) == 0) { sm[wid] = s; sm2[wid] = ss; }
    __syncthreads();
    s  = sm[0] + sm[1] + sm[2] + sm[3];
    ss = sm2[0] + sm2[1] + sm2[2] + sm2[3];
    float mean = s * (1.0f / DMODEL);
    float var  = ss * (1.0f / DMODEL) - mean * mean;
    float r = rsqrtf(var + EPS_LN);
    float* yp = Y + (size_t)row * DMODEL;
#pragma unroll
    for (int i = 0; i < 3; i++) {
        int c = t + i * 128;
        yp[c] = (v[i] - mean) * r * gg[c] + bb[c];
    }
}

// ================= Depthwise 3x3 conv + BN, stride 1 (Q path) ================
__global__ void convq_kernel(const float* __restrict__ xn, const float* __restrict__ w,
                             const float* __restrict__ cb, const float* __restrict__ g,
                             const float* __restrict__ bb, float* __restrict__ out) {
    int b = blockIdx.y, tok = blockIdx.x, c = threadIdx.x;
    int Wd, base;
    if (tok < NS_TOK) { Wd = 32; base = 0; } else { Wd = 16; base = NS_TOK; }
    int loc = tok - base;
    int oy = loc / Wd, ox = loc % Wd;
    const float* wp = w + c * 9;
    float acc = 0.f;
#pragma unroll
    for (int ky = 0; ky < 3; ky++) {
        int iy = oy - 1 + ky;
        if (iy < 0 || iy >= Wd) continue;
#pragma unroll
        for (int kx = 0; kx < 3; kx++) {
            int ix = ox - 1 + kx;
            if (ix < 0 || ix >= Wd) continue;
            acc += wp[ky * 3 + kx] * xn[((size_t)b * NTOK + base + iy * Wd + ix) * DMODEL + c];
        }
    }
    float sc = g[c] * rsqrtf(1.0f + EPS_BN);
    out[((size_t)b * NTOK + tok) * DMODEL + c] = (acc + cb[c]) * sc + bb[c];
}

// ============ Depthwise 3x3 conv + BN, stride 2, fused K & V =================
__global__ void convkv_kernel(const float* __restrict__ xn,
                              const float* __restrict__ wk, const float* __restrict__ cbk,
                              const float* __restrict__ gk, const float* __restrict__ bbk,
                              const float* __restrict__ wv, const float* __restrict__ cbv,
                              const float* __restrict__ gv, const float* __restrict__ bbv,
                              float* __restrict__ outk, float* __restrict__ outv) {
    int b = blockIdx.y, tok = blockIdx.x, c = threadIdx.x;
    int Wd, inW, inBase, base;
    if (tok < KV_S) { Wd = 16; inW = 32; inBase = 0; base = 0; }
    else            { Wd = 8;  inW = 16; inBase = NS_TOK; base = KV_S; }
    int loc = tok - base;
    int oy = loc / Wd, ox = loc % Wd;
    const float* wpk = wk + c * 9;
    const float* wpv = wv + c * 9;
    float acck = 0.f, accv = 0.f;
#pragma unroll
    for (int ky = 0; ky < 3; ky++) {
        int iy = 2 * oy - 1 + ky;
        if (iy < 0 || iy >= inW) continue;
#pragma unroll
        for (int kx = 0; kx < 3; kx++) {
            int ix = 2 * ox - 1 + kx;
            if (ix < 0 || ix >= inW) continue;
            float xv = xn[((size_t)b * NTOK + inBase + iy * inW + ix) * DMODEL + c];
            acck += wpk[ky * 3 + kx] * xv;
            accv += wpv[ky * 3 + kx] * xv;
        }
    }
    size_t oidx = ((size_t)b * KVTOK + tok) * DMODEL + c;
    outk[oidx] = (acck + cbk[c]) * (gk[c] * rsqrtf(1.0f + EPS_BN)) + bbk[c];
    outv[oidx] = (accv + cbv[c]) * (gv[c] * rsqrtf(1.0f + EPS_BN)) + bbv[c];
}

// ============ TF32 tensor-core GEMM, cp.async double-buffered ================
// C = A @ W^T + bias. A[M,K], W[N,K] row-major. 128x128 tile, BK=16, 2 stages.
#define BM 128
#define BN 128
#define BK2 16
#define GSTR 20   // 16+4 floats

template<int EPI>
__global__ void __launch_bounds__(256) gemm_tc(
        const float* __restrict__ A, const float* __restrict__ W,
        const float* __restrict__ bias, const float* __restrict__ resid,
        float* __restrict__ C, int M, int Nn, int Kk) {
    __shared__ __align__(16) float As[2][BM][GSTR];
    __shared__ __align__(16) float Ws[2][BN][GSTR];
    int t = threadIdx.x;
    int lane = t & 31, wid = t >> 5;
    int wm = (wid & 1) * 64;
    int wn = (wid >> 1) * 32;
    int bm = blockIdx.y * BM, bn = blockIdx.x * BN;
    int lr = lane >> 2, lc = lane & 3;

    float acc[4][4][4];
#pragma unroll
    for (int mi = 0; mi < 4; mi++)
#pragma unroll
        for (int ni = 0; ni < 4; ni++)
#pragma unroll
            for (int f = 0; f < 4; f++) acc[mi][ni][f] = 0.f;

    // per-thread load coords: 2 float4 per matrix per stage
    int r0 = t >> 2, c4 = (t & 3) * 4;          // rows 0..63
    int r1 = r0 + 64;                            // rows 64..127

    int niter = Kk / BK2;
    // prologue: stage 0
    {
        CP16(smem_u32(&As[0][r0][c4]), &A[(size_t)(bm + r0) * Kk + c4]);
        CP16(smem_u32(&As[0][r1][c4]), &A[(size_t)(bm + r1) * Kk + c4]);
        CP16(smem_u32(&Ws[0][r0][c4]), &W[(size_t)(bn + r0) * Kk + c4]);
        CP16(smem_u32(&Ws[0][r1][c4]), &W[(size_t)(bn + r1) * Kk + c4]);
        CPCOMMIT();
    }

    for (int it = 0; it < niter; it++) {
        int st = it & 1;
        if (it + 1 < niter) {
            int ns = st ^ 1;
            int k0 = (it + 1) * BK2;
            CP16(smem_u32(&As[ns][r0][c4]), &A[(size_t)(bm + r0) * Kk + k0 + c4]);
            CP16(smem_u32(&As[ns][r1][c4]), &A[(size_t)(bm + r1) * Kk + k0 + c4]);
            CP16(smem_u32(&Ws[ns][r0][c4]), &W[(size_t)(bn + r0) * Kk + k0 + c4]);
            CP16(smem_u32(&Ws[ns][r1][c4]), &W[(size_t)(bn + r1) * Kk + k0 + c4]);
            CPCOMMIT();
            asm volatile("cp.async.wait_group 1;");
        } else {
            asm volatile("cp.async.wait_group 0;");
        }
        __syncthreads();

#pragma unroll
        for (int ks = 0; ks < BK2; ks += 8) {
            uint32_t af[4][4], bf[4][2];
#pragma unroll
            for (int mi = 0; mi < 4; mi++) {
                int row = wm + mi * 16 + lr;
                af[mi][0] = f2tf32(As[st][row][ks + lc]);
                af[mi][1] = f2tf32(As[st][row + 8][ks + lc]);
                af[mi][2] = f2tf32(As[st][row][ks + lc + 4]);
                af[mi][3] = f2tf32(As[st][row + 8][ks + lc + 4]);
            }
#pragma unroll
            for (int ni = 0; ni < 4; ni++) {
                int n = wn + ni * 8 + lr;
                bf[ni][0] = f2tf32(Ws[st][n][ks + lc]);
                bf[ni][1] = f2tf32(Ws[st][n][ks + lc + 4]);
            }
#pragma unroll
            for (int mi = 0; mi < 4; mi++)
#pragma unroll
                for (int ni = 0; ni < 4; ni++)
                    mma_tf32(acc[mi][ni], af[mi], bf[ni][0], bf[ni][1]);
        }
        __syncthreads();
    }

    // epilogue
#pragma unroll
    for (int mi = 0; mi < 4; mi++) {
#pragma unroll
        for (int ni = 0; ni < 4; ni++) {
            int rr0 = bm + wm + mi * 16 + lr;
            int cc = bn + wn + ni * 8 + 2 * lc;
            float b0 = bias[cc], b1 = bias[cc + 1];
#pragma unroll
            for (int half = 0; half < 2; half++) {
                int r = rr0 + half * 8;
                float v0 = acc[mi][ni][half * 2 + 0] + b0;
                float v1 = acc[mi][ni][half * 2 + 1] + b1;
                if (EPI == 1) {
                    v0 = 0.5f * v0 * (1.0f + erff(v0 * 0.70710678118654752f));
                    v1 = 0.5f * v1 * (1.0f + erff(v1 * 0.70710678118654752f));
                } else if (EPI == 2) {
                    const float2 rv = *(const float2*)&resid[(size_t)r * Nn + cc];
                    v0 += rv.x; v1 += rv.y;
                }
                float2 ov = {v0, v1};
                *(float2*)&C[(size_t)r * Nn + cc] = ov;
            }
        }
    }
}

// ==================== TF32 tensor-core flash attention =======================
// Block: 128 threads (4 warps). Each warp owns 16 queries; block owns 64 and
// shares K/V smem tiles of 32 kv. Online softmax with register fragments.
__global__ void __launch_bounds__(128) attn_mma(
        const float* __restrict__ Q, const float* __restrict__ K,
        const float* __restrict__ V, const float* __restrict__ X,
        float* __restrict__ O, int q_off, int kv_off, int kv_len) {
    int b = blockIdx.z, h = blockIdx.y;
    int t = threadIdx.x;
    int w = t >> 5, lane = t & 31;
    int lr = lane >> 2, lc = lane & 3;
    int qbase = q_off + blockIdx.x * 64 + w * 16;

    __shared__ __align__(16) uint32_t ks_sm[32][52];
    __shared__ __align__(16) uint32_t vt_sm[HDIM][36];
    __shared__ __align__(16) float ps_sm[4][16][36];

    // Q fragments, scale folded in; resident across kv loop
    uint32_t aq[6][4];
#pragma unroll
    for (int kd = 0; kd < 6; kd++) {
        const float* qp0 = &Q[((size_t)(b * NTOK + qbase + lr)) * DMODEL + h * HDIM + kd * 8 + lc];
        const float* qp1 = qp0 + 8 * DMODEL;
        aq[kd][0] = f2tf32(qp0[0] * ATT_SCALE);
        aq[kd][1] = f2tf32(qp1[0] * ATT_SCALE);
        aq[kd][2] = f2tf32(qp0[4] * ATT_SCALE);
        aq[kd][3] = f2tf32(qp1[4] * ATT_SCALE);
    }

    float oacc[6][4];
#pragma unroll
    for (int ni = 0; ni < 6; ni++)
#pragma unroll
        for (int f = 0; f < 4; f++) oacc[ni][f] = 0.f;
    float m0 = -1e30f, m1 = -1e30f, l0 = 0.f, l1 = 0.f;

    for (int kt = 0; kt < kv_len; kt += 32) {
        // load K tile (row-major tf32) and V tile transposed
#pragma unroll
        for (int i = 0; i < 3; i++) {
            int e = t + i * 128;
            int r = e / 12, cc4 = (e % 12) * 4;
            size_t g = ((size_t)(b * KVTOK + kv_off + kt + r)) * DMODEL + h * HDIM + cc4;
            float4 kv4 = *(const float4*)&K[g];
            uint4 ku = {f2tf32(kv4.x), f2tf32(kv4.y), f2tf32(kv4.z), f2tf32(kv4.w)};
            *(uint4*)&ks_sm[r][cc4] = ku;
            float4 vv4 = *(const float4*)&V[g];
            vt_sm[cc4 + 0][r] = f2tf32(vv4.x);
            vt_sm[cc4 + 1][r] = f2tf32(vv4.y);
            vt_sm[cc4 + 2][r] = f2tf32(vv4.z);
            vt_sm[cc4 + 3][r] = f2tf32(vv4.w);
        }
        __syncthreads();

        // S = Q @ K^T  (16 x 32)
        float sacc[4][4];
#pragma unroll
        for (int ni = 0; ni < 4; ni++)
#pragma unroll
            for (int f = 0; f < 4; f++) sacc[ni][f] = 0.f;
#pragma unroll
        for (int kd = 0; kd < 6; kd++) {
#pragma unroll
            for (int ni = 0; ni < 4; ni++) {
                uint32_t b0 = ks_sm[ni * 8 + lr][kd * 8 + lc];
                uint32_t b1 = ks_sm[ni * 8 + lr][kd * 8 + lc + 4];
                mma_tf32(sacc[ni], aq[kd], b0, b1);
            }
        }

        // online softmax on fragments (rows lr and lr+8)
        float mt0 = -1e30f, mt1 = -1e30f;
#pragma unroll
        for (int ni = 0; ni < 4; ni++) {
            mt0 = fmaxf(mt0, fmaxf(sacc[ni][0], sacc[ni][1]));
            mt1 = fmaxf(mt1, fmaxf(sacc[ni][2], sacc[ni][3]));
        }
        mt0 = fmaxf(mt0, __shfl_xor_sync(0xffffffffu, mt0, 1));
        mt0 = fmaxf(mt0, __shfl_xor_sync(0xffffffffu, mt0, 2));
        mt1 = fmaxf(mt1, __shfl_xor_sync(0xffffffffu, mt1, 1));
        mt1 = fmaxf(mt1, __shfl_xor_sync(0xffffffffu, mt1, 2));
        float mn0 = fmaxf(m0, mt0), mn1 = fmaxf(m1, mt1);
        float cr0 = __expf(m0 - mn0), cr1 = __expf(m1 - mn1);
        float ps0 = 0.f, ps1 = 0.f;
#pragma unroll
        for (int ni = 0; ni < 4; ni++) {
            float p00 = __expf(sacc[ni][0] - mn0);
            float p01 = __expf(sacc[ni][1] - mn0);
            float p10 = __expf(sacc[ni][2] - mn1);
            float p11 = __expf(sacc[ni][3] - mn1);
            ps0 += p00 + p01; ps1 += p10 + p11;
            float2 w0 = {p00, p01};
            float2 w1 = {p10, p11};
            *(float2*)&ps_sm[w][lr][ni * 8 + 2 * lc] = w0;
            *(float2*)&ps_sm[w][lr + 8][ni * 8 + 2 * lc] = w1;
        }
        ps0 += __shfl_xor_sync(0xffffffffu, ps0, 1);
        ps0 += __shfl_xor_sync(0xffffffffu, ps0, 2);
        ps1 += __shfl_xor_sync(0xffffffffu, ps1, 1);
        ps1 += __shfl_xor_sync(0xffffffffu, ps1, 2);
        l0 = l0 * cr0 + ps0;
        l1 = l1 * cr1 + ps1;
        m0 = mn0; m1 = mn1;
#pragma unroll
        for (int ni = 0; ni < 6; ni++) {
            oacc[ni][0] *= cr0; oacc[ni][1] *= cr0;
            oacc[ni][2] *= cr1; oacc[ni][3] *= cr1;
        }
        __syncwarp();

        // O += P @ V   (16 x 48, k = 32)
#pragma unroll
        for (int kd = 0; kd < 4; kd++) {
            uint32_t ap[4];
            ap[0] = f2tf32(ps_sm[w][lr][kd * 8 + lc]);
            ap[1] = f2tf32(ps_sm[w][lr + 8][kd * 8 + lc]);
            ap[2] = f2tf32(ps_sm[w][lr][kd * 8 + lc + 4]);
            ap[3] = f2tf32(ps_sm[w][lr + 8][kd * 8 + lc + 4]);
#pragma unroll
            for (int ni = 0; ni < 6; ni++) {
                uint32_t b0 = vt_sm[ni * 8 + lr][kd * 8 + lc];
                uint32_t b1 = vt_sm[ni * 8 + lr][kd * 8 + lc + 4];
                mma_tf32(oacc[ni], ap, b0, b1);
            }
        }
        __syncthreads();
    }

    float rc0 = 1.0f / l0, rc1 = 1.0f / l1;
#pragma unroll
    for (int ni = 0; ni < 6; ni++) {
        int col = h * HDIM + ni * 8 + 2 * lc;
        size_t g0 = ((size_t)(b * NTOK + qbase + lr)) * DMODEL + col;
        size_t g1 = g0 + (size_t)8 * DMODEL;
        float2 x0 = *(const float2*)&X[g0];
        float2 x1 = *(const float2*)&X[g1];
        float2 o0 = {x0.x + oacc[ni][0] * rc0, x0.y + oacc[ni][1] * rc0};
        float2 o1 = {x1.x + oacc[ni][2] * rc1, x1.y + oacc[ni][3] * rc1};
        *(float2*)&O[g0] = o0;
        *(float2*)&O[g1] = o1;
    }
}

// ================================ launch =====================================
extern "C" void kernel_launch(void* const* d_in, const int* in_sizes, int n_in,
                              void* d_out, int out_size) {
    const float* x     = (const float*)d_in[0];
    const float* ln1_g = (const float*)d_in[1];
    const float* ln1_b = (const float*)d_in[2];
    const float* dwq_w = (const float*)d_in[3];
    const float* dwq_b = (const float*)d_in[4];
    const float* bnq_g = (const float*)d_in[5];
    const float* bnq_b = (const float*)d_in[6];
    const float* dwk_w = (const float*)d_in[7];
    const float* dwk_b = (const float*)d_in[8];
    const float* bnk_g = (const float*)d_in[9];
    const float* bnk_b = (const float*)d_in[10];
    const float* dwv_w = (const float*)d_in[11];
    const float* dwv_b = (const float*)d_in[12];
    const float* bnv_g = (const float*)d_in[13];
    const float* bnv_b = (const float*)d_in[14];
    const float* pq_w  = (const float*)d_in[15];
    const float* pq_b  = (const float*)d_in[16];
    const float* pk_w  = (const float*)d_in[17];
    const float* pk_b  = (const float*)d_in[18];
    const float* pv_w  = (const float*)d_in[19];
    const float* pv_b  = (const float*)d_in[20];
    const float* ln2_g = (const float*)d_in[21];
    const float* ln2_b = (const float*)d_in[22];
    const float* ff1_w = (const float*)d_in[23];
    const float* ff1_b = (const float*)d_in[24];
    const float* ff2_w = (const float*)d_in[25];
    const float* ff2_b = (const float*)d_in[26];
    float* out = (float*)d_out;

    float *xn, *cq, *ck, *cv, *q, *k, *v, *x1, *l2, *hbuf;
    cudaGetSymbolAddress((void**)&xn,   g_xn);
    cudaGetSymbolAddress((void**)&cq,   g_cq);
    cudaGetSymbolAddress((void**)&ck,   g_ck);
    cudaGetSymbolAddress((void**)&cv,   g_cv);
    cudaGetSymbolAddress((void**)&q,    g_q);
    cudaGetSymbolAddress((void**)&k,    g_k);
    cudaGetSymbolAddress((void**)&v,    g_v);
    cudaGetSymbolAddress((void**)&x1,   g_x1);
    cudaGetSymbolAddress((void**)&l2,   g_l2);
    cudaGetSymbolAddress((void**)&hbuf, g_h);

    const int Mq = BATCH * NTOK;    // 40960
    const int Mkv = BATCH * KVTOK;  // 10240

    ln_kernel<<<Mq, 128>>>(x, ln1_g, ln1_b, xn);
    convq_kernel<<<dim3(NTOK, BATCH), DMODEL>>>(xn, dwq_w, dwq_b, bnq_g, bnq_b, cq);
    convkv_kernel<<<dim3(KVTOK, BATCH), DMODEL>>>(xn, dwk_w, dwk_b, bnk_g, bnk_b,
                                                  dwv_w, dwv_b, bnv_g, bnv_b, ck, cv);
    gemm_tc<0><<<dim3(DMODEL / BN, Mq / BM), 256>>>(cq, pq_w, pq_b, nullptr, q, Mq, DMODEL, DMODEL);
    gemm_tc<0><<<dim3(DMODEL / BN, Mkv / BM), 256>>>(ck, pk_w, pk_b, nullptr, k, Mkv, DMODEL, DMODEL);
    gemm_tc<0><<<dim3(DMODEL / BN, Mkv / BM), 256>>>(cv, pv_w, pv_b, nullptr, v, Mkv, DMODEL, DMODEL);
    attn_mma<<<dim3(NS_TOK / 64, NHEAD, BATCH), 128>>>(q, k, v, x, x1, 0, 0, KVTOK);
    attn_mma<<<dim3(NT_TOK / 64, NHEAD, BATCH), 128>>>(q, k, v, x, x1, NS_TOK, KV_S, KV_T);
    ln_kernel<<<Mq, 128>>>(x1, ln2_g, ln2_b, l2);
    gemm_tc<1><<<dim3(FFDIM / BN, Mq / BM), 256>>>(l2, ff1_w, ff1_b, nullptr, hbuf, Mq, FFDIM, DMODEL);
    gemm_tc<2><<<dim3(DMODEL / BN, Mq / BM), 256>>>(hbuf, ff2_w, ff2_b, x1, out, Mq, DMODEL, FFDIM);
}